// round 1
// baseline (speedup 1.0000x reference)
#include <cuda_runtime.h>
#include <cstdint>
#include <cmath>

#define T_STEPS 4096
#define HH      1024
#define G4      4096          // 4*H gate rows
#define NCTA    128
#define UPC     8             // hidden units per CTA (1024/128)
#define IND     64
#define OUTD    64

// ---------------- scratch (static __device__ — no allocation allowed) -------
__device__ float g_Wc0[G4 * IND];              // W_ih0 @ W_in   (4096 x 64)
__device__ float g_bc0[G4];                    // W_ih0@b_in + b_ih0 + b_hh0
__device__ float g_pre0[T_STEPS * G4];         // 64 MB
__device__ float g_pre1[T_STEPS * G4];         // 64 MB
__device__ float g_H0[T_STEPS * HH];           // 16 MB
__device__ float g_H1[T_STEPS * HH];           // 16 MB
__device__ unsigned int g_ctr;

// ---------------- counter reset ---------------------------------------------
__global__ void k_reset() { g_ctr = 0u; }

// ---------------- Wc0 = W_ih0 @ W_in  (4096x1024 @ 1024x64 -> 4096x64) ------
__global__ __launch_bounds__(256) void k_wc0(const float* __restrict__ Wih0,
                                             const float* __restrict__ Win) {
    int tid = threadIdx.x;
    int tx = tid & 63;          // output col d
    int ty = tid >> 6;          // row within group of 4
    int r = blockIdx.x * 4 + ty;
    const float* wr = Wih0 + (size_t)r * HH;
    float acc = 0.f;
    for (int k = 0; k < HH; ++k)
        acc = fmaf(__ldg(&wr[k]), __ldg(&Win[k * IND + tx]), acc);
    g_Wc0[r * IND + tx] = acc;
}

// ---------------- bc0 = W_ih0 @ b_in + b_ih0 + b_hh0 ------------------------
__global__ __launch_bounds__(256) void k_bc0(const float* __restrict__ Wih0,
                                             const float* __restrict__ b_in,
                                             const float* __restrict__ b_ih0,
                                             const float* __restrict__ b_hh0) {
    int r = blockIdx.x * 256 + threadIdx.x;
    const float* wr = Wih0 + (size_t)r * HH;
    float acc = 0.f;
    for (int k = 0; k < HH; ++k)
        acc = fmaf(wr[k], __ldg(&b_in[k]), acc);
    g_bc0[r] = acc + b_ih0[r] + b_hh0[r];
}

// ---------------- pre0 = x @ Wc0^T + bc0   (M=4096, N=4096, K=64) -----------
// x[t][d] = inputs[s=t&31][step=t>>5][d]   (step-major flattening)
__global__ __launch_bounds__(256) void k_pre0(const float* __restrict__ inp) {
    __shared__ float Xs[64][IND];
    __shared__ float Ws[64][IND];
    int tid = threadIdx.x;
    int t0 = blockIdx.y * 64;
    int r0 = blockIdx.x * 64;

    #pragma unroll
    for (int i = 0; i < 16; ++i) {
        int idx = tid + i * 256;
        int tr = idx >> 6, d = idx & 63;
        int t = t0 + tr;
        int s = t & 31, st = t >> 5;
        Xs[tr][d] = inp[((size_t)s * 128 + st) * 64 + d];
        Ws[tr][d] = g_Wc0[(r0 + tr) * IND + d];
    }
    __syncthreads();

    int tx = tid & 15, ty = tid >> 4;
    float acc[4][4] = {};
    for (int d = 0; d < 64; ++d) {
        float a[4], b[4];
        #pragma unroll
        for (int i = 0; i < 4; ++i) a[i] = Xs[ty * 4 + i][d];
        #pragma unroll
        for (int j = 0; j < 4; ++j) b[j] = Ws[tx * 4 + j][d];
        #pragma unroll
        for (int i = 0; i < 4; ++i)
            #pragma unroll
            for (int j = 0; j < 4; ++j)
                acc[i][j] = fmaf(a[i], b[j], acc[i][j]);
    }
    #pragma unroll
    for (int i = 0; i < 4; ++i) {
        int t = t0 + ty * 4 + i;
        #pragma unroll
        for (int j = 0; j < 4; ++j) {
            int r = r0 + tx * 4 + j;
            g_pre0[(size_t)t * G4 + r] = acc[i][j] + g_bc0[r];
        }
    }
}

// ---------------- persistent LSTM chain -------------------------------------
// 128 CTAs x 1024 threads, all grid-resident (128 <= 148 SMs, 1 CTA/SM).
// CTA b owns units [b*8, b*8+8). warp w: unit = w>>2, K-quarter q = w&3.
// Each lane holds 32 fp32 weights (4 gates x 8 k) in registers.
__device__ __forceinline__ float sigf(float x) { return 1.f / (1.f + expf(-x)); }

__global__ __launch_bounds__(1024) void k_chain(const float* __restrict__ Whh,
                                                const float* __restrict__ pre,
                                                float* __restrict__ Hout) {
    int tid = threadIdx.x;
    int w = tid >> 5, l = tid & 31;
    int b = blockIdx.x;
    int ubase = b * UPC;
    int ul = w >> 2;          // local unit 0..7
    int q  = w & 3;           // k-quarter 0..3
    int unit = ubase + ul;
    int koff = q * 256 + l * 8;

    __shared__ float h_s[HH];
    __shared__ float pacc[32 * 128];   // [row_local 0..31][q*32+l]
    __shared__ float gates[32];
    __shared__ float c_s[UPC];

    // load weights into registers (coalesced: warp covers 256 consecutive floats)
    float4 wv[4][2];
    #pragma unroll
    for (int g = 0; g < 4; ++g) {
        const float* wr = Whh + (size_t)(g * HH + unit) * HH + koff;
        wv[g][0] = *(const float4*)(wr);
        wv[g][1] = *(const float4*)(wr + 4);
    }

    h_s[tid] = 0.f;
    if (tid < UPC) c_s[tid] = 0.f;
    __syncthreads();

    unsigned int* ctr = &g_ctr;

    for (int t = 0; t < T_STEPS; ++t) {
        // --- partial matvec: 4 gate rows x 8 k-values per lane --------------
        float4 hv0 = *(const float4*)&h_s[koff];
        float4 hv1 = *(const float4*)&h_s[koff + 4];
        float acc[4];
        #pragma unroll
        for (int g = 0; g < 4; ++g) {
            float a = 0.f;
            a = fmaf(wv[g][0].x, hv0.x, a);
            a = fmaf(wv[g][0].y, hv0.y, a);
            a = fmaf(wv[g][0].z, hv0.z, a);
            a = fmaf(wv[g][0].w, hv0.w, a);
            a = fmaf(wv[g][1].x, hv1.x, a);
            a = fmaf(wv[g][1].y, hv1.y, a);
            a = fmaf(wv[g][1].z, hv1.z, a);
            a = fmaf(wv[g][1].w, hv1.w, a);
            acc[g] = a;
        }
        #pragma unroll
        for (int g = 0; g < 4; ++g)
            pacc[(ul * 4 + g) * 128 + q * 32 + l] = acc[g];
        __syncthreads();

        // --- reduce: warp w reduces row_local = w ---------------------------
        {
            float s = pacc[w * 128 + l] + pacc[w * 128 + 32 + l]
                    + pacc[w * 128 + 64 + l] + pacc[w * 128 + 96 + l];
            s += __shfl_xor_sync(0xffffffffu, s, 16);
            s += __shfl_xor_sync(0xffffffffu, s, 8);
            s += __shfl_xor_sync(0xffffffffu, s, 4);
            s += __shfl_xor_sync(0xffffffffu, s, 2);
            s += __shfl_xor_sync(0xffffffffu, s, 1);
            if (l == 0) {
                int gg = w & 3, uu = w >> 2;
                int grow = gg * HH + ubase + uu;
                gates[w] = s + __ldg(&pre[(size_t)t * G4 + grow]);
            }
        }
        __syncthreads();

        // --- LSTM cell for this CTA's 8 units -------------------------------
        if (tid < UPC) {
            float gi = gates[tid * 4 + 0];
            float gf = gates[tid * 4 + 1];
            float gc = gates[tid * 4 + 2];
            float go = gates[tid * 4 + 3];
            float c = sigf(gf) * c_s[tid] + sigf(gi) * tanhf(gc);
            c_s[tid] = c;
            float h = sigf(go) * tanhf(c);
            Hout[(size_t)t * HH + ubase + tid] = h;
        }
        __threadfence();
        __syncthreads();

        // --- chip-wide sync: counter arrive + acquire poll ------------------
        if (tid == 0) {
            atomicAdd(ctr, 1u);
            unsigned int target = (unsigned int)(t + 1) * (unsigned int)NCTA;
            unsigned int v;
            do {
                asm volatile("ld.acquire.gpu.global.u32 %0, [%1];"
                             : "=r"(v) : "l"(ctr) : "memory");
            } while (v < target);
        }
        __syncthreads();

        // --- broadcast: reload full h(t) from L2 ----------------------------
        h_s[tid] = __ldcg(&Hout[(size_t)t * HH + tid]);
        __syncthreads();
    }
}

// ---------------- pre1 = H0 @ W_ih1^T + (b_ih1 + b_hh1) ---------------------
// M=N=4096, K=1024, fp32, 128x128 tile, 8x8 micro, double-buffered smem.
__global__ __launch_bounds__(256) void k_pre1(const float* __restrict__ A,
                                              const float* __restrict__ B,
                                              const float* __restrict__ b1a,
                                              const float* __restrict__ b1b) {
    __shared__ float As[2][8][132];
    __shared__ float Bs[2][8][132];
    int tid = threadIdx.x;
    int m0 = blockIdx.y * 128;
    int n0 = blockIdx.x * 128;
    int lm = tid >> 1;           // 0..127
    int kq = (tid & 1) * 4;      // 0 or 4
    int tx = tid & 15, ty = tid >> 4;

    const float* Ap = A + (size_t)(m0 + lm) * HH + kq;
    const float* Bp = B + (size_t)(n0 + lm) * HH + kq;

    float4 ra = *(const float4*)Ap;
    float4 rb = *(const float4*)Bp;
    As[0][kq + 0][lm] = ra.x; As[0][kq + 1][lm] = ra.y;
    As[0][kq + 2][lm] = ra.z; As[0][kq + 3][lm] = ra.w;
    Bs[0][kq + 0][lm] = rb.x; Bs[0][kq + 1][lm] = rb.y;
    Bs[0][kq + 2][lm] = rb.z; Bs[0][kq + 3][lm] = rb.w;
    __syncthreads();

    float acc[8][8] = {};
    const int nk = HH / 8;       // 128
    for (int kt = 0; kt < nk; ++kt) {
        int buf = kt & 1;
        if (kt + 1 < nk) {
            ra = *(const float4*)(Ap + (kt + 1) * 8);
            rb = *(const float4*)(Bp + (kt + 1) * 8);
        }
        #pragma unroll
        for (int kk = 0; kk < 8; ++kk) {
            float a[8], bb[8];
            *(float4*)&a[0]  = *(const float4*)&As[buf][kk][ty * 8];
            *(float4*)&a[4]  = *(const float4*)&As[buf][kk][ty * 8 + 4];
            *(float4*)&bb[0] = *(const float4*)&Bs[buf][kk][tx * 8];
            *(float4*)&bb[4] = *(const float4*)&Bs[buf][kk][tx * 8 + 4];
            #pragma unroll
            for (int i = 0; i < 8; ++i)
                #pragma unroll
                for (int j = 0; j < 8; ++j)
                    acc[i][j] = fmaf(a[i], bb[j], acc[i][j]);
        }
        __syncthreads();
        if (kt + 1 < nk) {
            int nb = buf ^ 1;
            As[nb][kq + 0][lm] = ra.x; As[nb][kq + 1][lm] = ra.y;
            As[nb][kq + 2][lm] = ra.z; As[nb][kq + 3][lm] = ra.w;
            Bs[nb][kq + 0][lm] = rb.x; Bs[nb][kq + 1][lm] = rb.y;
            Bs[nb][kq + 2][lm] = rb.z; Bs[nb][kq + 3][lm] = rb.w;
            __syncthreads();
        }
    }

    float bias[8];
    #pragma unroll
    for (int j = 0; j < 8; ++j) {
        int n = n0 + tx * 8 + j;
        bias[j] = __ldg(&b1a[n]) + __ldg(&b1b[n]);
    }
    #pragma unroll
    for (int i = 0; i < 8; ++i) {
        int m = m0 + ty * 8 + i;
        float4 o0, o1;
        o0.x = acc[i][0] + bias[0]; o0.y = acc[i][1] + bias[1];
        o0.z = acc[i][2] + bias[2]; o0.w = acc[i][3] + bias[3];
        o1.x = acc[i][4] + bias[4]; o1.y = acc[i][5] + bias[5];
        o1.z = acc[i][6] + bias[6]; o1.w = acc[i][7] + bias[7];
        *(float4*)&g_pre1[(size_t)m * G4 + n0 + tx * 8]     = o0;
        *(float4*)&g_pre1[(size_t)m * G4 + n0 + tx * 8 + 4] = o1;
    }
}

// ---------------- y = H1 @ W_out^T + b_out, reorder to (S, steps, O) --------
__global__ __launch_bounds__(256) void k_out(const float* __restrict__ Wout,
                                             const float* __restrict__ bout,
                                             float* __restrict__ out) {
    __shared__ float hs[HH];
    int t = blockIdx.x;
    int tid = threadIdx.x;
    #pragma unroll
    for (int i = 0; i < 4; ++i)
        hs[tid + i * 256] = g_H1[(size_t)t * HH + tid + i * 256];
    __syncthreads();

    int w = tid >> 5, l = tid & 31;
    int s = t & 31, st = t >> 5;
    float* orow = out + ((size_t)s * 128 + st) * 64;
    #pragma unroll
    for (int oi = 0; oi < 8; ++oi) {
        int o = w * 8 + oi;
        const float* wr = Wout + (size_t)o * HH;
        float acc = 0.f;
        #pragma unroll
        for (int j = 0; j < 32; ++j)
            acc = fmaf(__ldg(&wr[l + 32 * j]), hs[l + 32 * j], acc);
        acc += __shfl_xor_sync(0xffffffffu, acc, 16);
        acc += __shfl_xor_sync(0xffffffffu, acc, 8);
        acc += __shfl_xor_sync(0xffffffffu, acc, 4);
        acc += __shfl_xor_sync(0xffffffffu, acc, 2);
        acc += __shfl_xor_sync(0xffffffffu, acc, 1);
        if (l == 0) orow[o] = acc + __ldg(&bout[o]);
    }
}

// ---------------- launch ----------------------------------------------------
extern "C" void kernel_launch(void* const* d_in, const int* in_sizes, int n_in,
                              void* d_out, int out_size) {
    const float* inp   = (const float*)d_in[0];
    const float* W_in  = (const float*)d_in[1];
    const float* b_in  = (const float*)d_in[2];
    const float* W_ih0 = (const float*)d_in[3];
    const float* W_hh0 = (const float*)d_in[4];
    const float* b_ih0 = (const float*)d_in[5];
    const float* b_hh0 = (const float*)d_in[6];
    const float* W_ih1 = (const float*)d_in[7];
    const float* W_hh1 = (const float*)d_in[8];
    const float* b_ih1 = (const float*)d_in[9];
    const float* b_hh1 = (const float*)d_in[10];
    const float* W_out = (const float*)d_in[11];
    const float* b_out = (const float*)d_in[12];
    float* out = (float*)d_out;

    float *pre0, *pre1, *H0, *H1;
    cudaGetSymbolAddress((void**)&pre0, g_pre0);
    cudaGetSymbolAddress((void**)&pre1, g_pre1);
    cudaGetSymbolAddress((void**)&H0, g_H0);
    cudaGetSymbolAddress((void**)&H1, g_H1);

    // input-path GEMMs (K collapsed to 64 via Wc0 = W_ih0 @ W_in)
    k_wc0<<<G4 / 4, 256>>>(W_ih0, W_in);
    k_bc0<<<G4 / 256, 256>>>(W_ih0, b_in, b_ih0, b_hh0);
    k_pre0<<<dim3(64, 64), 256>>>(inp);

    // layer-0 sequential chain
    k_reset<<<1, 1>>>();
    k_chain<<<NCTA, 1024>>>(W_hh0, pre0, H0);

    // layer-1 input contributions (big fp32 GEMM)
    k_pre1<<<dim3(32, 32), 256>>>(H0, W_ih1, b_ih1, b_hh1);

    // layer-1 sequential chain
    k_reset<<<1, 1>>>();
    k_chain<<<NCTA, 1024>>>(W_hh1, pre1, H1);

    // output projection + (samples, steps, out) reorder
    k_out<<<T_STEPS, 256>>>(W_out, b_out, out);
}